// round 15
// baseline (speedup 1.0000x reference)
#include <cuda_runtime.h>
#include <math.h>
#include <cstdint>

#define NN    100000
#define EE    3200000
#define NFEAT 256
#define NHID  128
#define NCLASS 40

// ---------------- scratch ----------------
__device__ __align__(16) unsigned short g_s1h[NN * NHID];   // x @ W1, fp16 (25.6 MB)
__device__ __align__(16) unsigned short g_hh [NN * NHID];   // relu(A@s1+b1), fp16 (25.6 MB)
__device__ __align__(16) unsigned short g_s2h[NN * NCLASS]; // h @ W2, fp16 (8 MB)
__device__ int g_rowptr[NN + 1];
// W1 bf16 hi/lo fragment image for m16n8k16
__device__ __align__(16) uint32_t g_Bbf[32768];             // 128 KB

// ---------------- f32x2 packed helpers ----------------
__device__ __forceinline__ unsigned long long ffma2(unsigned long long a,
                                                    unsigned long long b,
                                                    unsigned long long c) {
    unsigned long long d;
    asm("fma.rn.f32x2 %0, %1, %2, %3;" : "=l"(d) : "l"(a), "l"(b), "l"(c));
    return d;
}
__device__ __forceinline__ unsigned long long dup2(float a) {
    unsigned long long d;
    asm("mov.b64 %0, {%1, %1};" : "=l"(d) : "f"(a));
    return d;
}
__device__ __forceinline__ unsigned long long packf2(float2 f) {
    unsigned long long d;
    asm("mov.b64 %0, {%1, %2};" : "=l"(d) : "f"(f.x), "f"(f.y));
    return d;
}
__device__ __forceinline__ float2 unpack2(unsigned long long v) {
    float2 f;
    asm("mov.b64 {%0, %1}, %2;" : "=f"(f.x), "=f"(f.y) : "l"(v));
    return f;
}
__device__ __forceinline__ unsigned long long ldg64cg(const void* p) {
    unsigned long long v;
    asm volatile("ld.global.cg.b64 %0, [%1];" : "=l"(v) : "l"(p));
    return v;
}

// ---------------- fp16 storage helpers ----------------
__device__ __forceinline__ uint32_t packf16(float2 v) {      // low16 = f16(v.x)
    uint32_t d;
    asm("cvt.rn.f16x2.f32 %0, %1, %2;" : "=r"(d) : "f"(v.y), "f"(v.x));
    return d;
}
__device__ __forceinline__ float2 unpackf16(uint32_t h) {
    float2 f;
    asm("{\n\t.reg .b16 lo, hi;\n\t"
        "mov.b32 {lo, hi}, %2;\n\t"
        "cvt.f32.f16 %0, lo;\n\t"
        "cvt.f32.f16 %1, hi;\n\t}"
        : "=f"(f.x), "=f"(f.y) : "r"(h));
    return f;
}

// ---------------- cp.async helpers ----------------
__device__ __forceinline__ void cpa16(unsigned dst, const void* src, bool pred) {
    int sz = pred ? 16 : 0;
    asm volatile("cp.async.ca.shared.global [%0], [%1], 16, %2;\n"
                 :: "r"(dst), "l"(src), "r"(sz));
}
__device__ __forceinline__ void cpa_commit() { asm volatile("cp.async.commit_group;\n"); }
__device__ __forceinline__ void cpa_wait1()  { asm volatile("cp.async.wait_group 1;\n"); }
__device__ __forceinline__ void cpa_wait0()  { asm volatile("cp.async.wait_group 0;\n"); }

// ---------------- bf16 helpers (gemm1 hi/lo split) ----------------
__device__ __forceinline__ uint32_t pack2bf(float2 v) {
    uint32_t d;
    asm("cvt.rn.bf16x2.f32 %0, %1, %2;" : "=r"(d) : "f"(v.y), "f"(v.x));
    return d;
}
__device__ __forceinline__ uint32_t pack2bf_lo(float2 v, uint32_t h) {
    float fx = __uint_as_float(h << 16);
    float fy = __uint_as_float(h & 0xFFFF0000u);
    float2 r = make_float2(v.x - fx, v.y - fy);
    return pack2bf(r);
}
#define MMA_BF16(d, a0, a1, a2, a3, b0, b1)                                      \
    asm volatile("mma.sync.aligned.m16n8k16.row.col.f32.bf16.bf16.f32 "         \
        "{%0,%1,%2,%3}, {%4,%5,%6,%7}, {%8,%9}, {%0,%1,%2,%3};"                 \
        : "+f"((d)[0]), "+f"((d)[1]), "+f"((d)[2]), "+f"((d)[3])                \
        : "r"(a0), "r"(a1), "r"(a2), "r"(a3), "r"(b0), "r"(b1))

// ---------------- CSR row_ptr ----------------
__global__ void build_rowptr_kernel(const int* __restrict__ arow) {
    int r = blockIdx.x * blockDim.x + threadIdx.x;
    if (r > NN) return;
    int lo = 0, hi = EE;
    while (lo < hi) {
        int mid = (lo + hi) >> 1;
        if (arow[mid] < r) lo = mid + 1; else hi = mid;
    }
    g_rowptr[r] = lo;
}

// ---------------- W1 -> bf16 hi/lo fragment image (m16n8k16, col-major B) ----------------
__global__ void w1bf16_kernel(const float* __restrict__ W1) {
    int idx = blockIdx.x * blockDim.x + threadIdx.x;
    if (idx >= NFEAT * NHID) return;
    int k = idx >> 7, n = idx & 127;
    float w = W1[idx];
    uint32_t hp = pack2bf(make_float2(w, 0.f));
    unsigned short hi16 = (unsigned short)(hp & 0xFFFFu);
    float fh = __uint_as_float((uint32_t)hi16 << 16);
    uint32_t lp = pack2bf(make_float2(w - fh, 0.f));
    unsigned short lo16 = (unsigned short)(lp & 0xFFFFu);

    int c16 = k >> 4, kk = k & 15;
    int ct = n >> 3, gid = n & 7;
    int reg = kk >> 3;
    int tig = (kk & 7) >> 1;
    int pos = kk & 1;
    int lane = gid * 4 + tig;
    int base16 = ((((c16 * 16 + ct) * 2 + 0) * 32 + lane) * 2 + reg) * 2 + pos;
    unsigned short* B16 = (unsigned short*)g_Bbf;
    B16[base16]       = hi16;     // h = 0
    B16[base16 + 128] = lo16;     // h = 1
}

// ---------------- GEMM1 (mma.sync bf16 hi/lo): g_s1h = fp16(X @ W1) ----------------
__global__ void __launch_bounds__(512) gemm1_bf16_kernel(const float* __restrict__ X) {
    __shared__ __align__(16) uint32_t sB[2][4096];   // 2 x 16KB

    const int tid  = threadIdx.x;
    const int lane = tid & 31;
    const int warp = tid >> 5;
    const int wrow = (warp >> 1) * 16;
    const int wcol = (warp & 1) * 64;
    const int row0 = blockIdx.x * 128;
    const int gid  = lane >> 2;
    const int tig  = lane & 3;
    const int ctb  = wcol >> 3;

    unsigned sb_addr = (unsigned)__cvta_generic_to_shared(&sB[0][0]);

    int rowi[2];
    bool rokg[2];
#pragma unroll
    for (int p = 0; p < 2; p++) {
        rowi[p] = row0 + wrow + gid + p * 8;
        rokg[p] = rowi[p] < NN;
    }

    float acc[8][4];
#pragma unroll
    for (int c = 0; c < 8; c++)
#pragma unroll
        for (int j = 0; j < 4; j++) acc[c][j] = 0.f;

#define G1_PREFETCH(stage, s)                                                    \
    do {                                                                         \
        _Pragma("unroll")                                                        \
        for (int j = 0; j < 2; j++) {                                            \
            int off = (j * 512 + tid) * 16;                                      \
            cpa16(sb_addr + (stage) * 16384 + off,                               \
                  (const char*)g_Bbf + (s) * 16384 + off, true);                 \
        }                                                                        \
        cpa_commit();                                                            \
    } while (0)

#define G1_LOAD_A(dst, s_)                                                       \
    do {                                                                         \
        _Pragma("unroll")                                                        \
        for (int sub = 0; sub < 2; sub++)                                        \
            _Pragma("unroll")                                                    \
            for (int p = 0; p < 2; p++)                                          \
                _Pragma("unroll")                                                \
                for (int q = 0; q < 2; q++) {                                    \
                    int kidx = (s_) * 32 + sub * 16 + tig * 2 + q * 8;           \
                    (dst)[sub][p][q] = rokg[p]                                   \
                        ? __ldg((const float2*)&X[(size_t)rowi[p] * NFEAT + kidx]) \
                        : make_float2(0.f, 0.f);                                 \
                }                                                                \
    } while (0)

    float2 srcA[2][2][2], srcB[2][2][2];
    G1_LOAD_A(srcA, 0);
    G1_PREFETCH(0, 0);

    for (int s = 0; s < 8; s++) {
        if (s + 1 < 8) {
            G1_PREFETCH((s + 1) & 1, s + 1);
            if (s & 1) G1_LOAD_A(srcA, s + 1); else G1_LOAD_A(srcB, s + 1);
            cpa_wait1();
        } else {
            cpa_wait0();
        }
        __syncthreads();

        float2 (*cur)[2][2] = (s & 1) ? srcB : srcA;
        const uint2* Bst = (const uint2*)&sB[s & 1][0];
#pragma unroll
        for (int sub = 0; sub < 2; sub++) {
            uint32_t ah[4], al[4];
            ah[0] = pack2bf(cur[sub][0][0]);
            ah[1] = pack2bf(cur[sub][1][0]);
            ah[2] = pack2bf(cur[sub][0][1]);
            ah[3] = pack2bf(cur[sub][1][1]);
            al[0] = pack2bf_lo(cur[sub][0][0], ah[0]);
            al[1] = pack2bf_lo(cur[sub][1][0], ah[1]);
            al[2] = pack2bf_lo(cur[sub][0][1], ah[2]);
            al[3] = pack2bf_lo(cur[sub][1][1], ah[3]);
#pragma unroll
            for (int c = 0; c < 8; c++) {
                int ctg = ctb + c;
                uint2 bhi = Bst[sub * 1024 + (ctg * 2 + 0) * 32 + lane];
                uint2 blo = Bst[sub * 1024 + (ctg * 2 + 1) * 32 + lane];
                MMA_BF16(acc[c], ah[0], ah[1], ah[2], ah[3], bhi.x, bhi.y);
                MMA_BF16(acc[c], ah[0], ah[1], ah[2], ah[3], blo.x, blo.y);
                MMA_BF16(acc[c], al[0], al[1], al[2], al[3], bhi.x, bhi.y);
            }
        }
        __syncthreads();
    }

#pragma unroll
    for (int c = 0; c < 8; c++) {
        int col = wcol + c * 8 + tig * 2;
        if (rokg[0])
            *(uint32_t*)&g_s1h[(size_t)rowi[0] * NHID + col] =
                packf16(make_float2(acc[c][0], acc[c][1]));
        if (rokg[1])
            *(uint32_t*)&g_s1h[(size_t)rowi[1] * NHID + col] =
                packf16(make_float2(acc[c][2], acc[c][3]));
    }
#undef G1_PREFETCH
#undef G1_LOAD_A
}

// ---------------- SpMM1 + bias + ReLU (warp/row, fp16 gathers, 4-edge unroll) ----------------
__global__ void spmm1_kernel(const int* __restrict__ acol, const float* __restrict__ aval,
                             const float* __restrict__ b1) {
    int warp = (blockIdx.x * blockDim.x + threadIdx.x) >> 5;
    int lane = threadIdx.x & 31;
    if (warp >= NN) return;

    int s = g_rowptr[warp];
    int e = g_rowptr[warp + 1];

    const char* S1b = (const char*)g_s1h + (size_t)lane * 8;   // row stride 256B
    unsigned long long a01 = 0ull, a23 = 0ull;

    int i = s;
    while (i < e && (i & 3)) {              // peel to 4-alignment
        int   c = __ldcs(&acol[i]);
        float v = __ldcs(&aval[i]);
        unsigned long long w = ldg64cg(S1b + (size_t)c * 256);
        unsigned long long vv = dup2(v);
        a01 = ffma2(vv, packf2(unpackf16((uint32_t)w)), a01);
        a23 = ffma2(vv, packf2(unpackf16((uint32_t)(w >> 32))), a23);
        i++;
    }
    for (; i + 3 < e; i += 4) {             // 4 gathers in flight
        int4   c4 = __ldcs((const int4*)&acol[i]);
        float4 v4 = __ldcs((const float4*)&aval[i]);
        unsigned long long w0 = ldg64cg(S1b + (size_t)c4.x * 256);
        unsigned long long w1 = ldg64cg(S1b + (size_t)c4.y * 256);
        unsigned long long w2 = ldg64cg(S1b + (size_t)c4.z * 256);
        unsigned long long w3 = ldg64cg(S1b + (size_t)c4.w * 256);
        unsigned long long va = dup2(v4.x), vb = dup2(v4.y);
        unsigned long long vc = dup2(v4.z), vd = dup2(v4.w);
        a01 = ffma2(va, packf2(unpackf16((uint32_t)w0)), a01);
        a23 = ffma2(va, packf2(unpackf16((uint32_t)(w0 >> 32))), a23);
        a01 = ffma2(vb, packf2(unpackf16((uint32_t)w1)), a01);
        a23 = ffma2(vb, packf2(unpackf16((uint32_t)(w1 >> 32))), a23);
        a01 = ffma2(vc, packf2(unpackf16((uint32_t)w2)), a01);
        a23 = ffma2(vc, packf2(unpackf16((uint32_t)(w2 >> 32))), a23);
        a01 = ffma2(vd, packf2(unpackf16((uint32_t)w3)), a01);
        a23 = ffma2(vd, packf2(unpackf16((uint32_t)(w3 >> 32))), a23);
    }
    for (; i < e; i++) {
        int   c = __ldcs(&acol[i]);
        float v = __ldcs(&aval[i]);
        unsigned long long w = ldg64cg(S1b + (size_t)c * 256);
        unsigned long long vv = dup2(v);
        a01 = ffma2(vv, packf2(unpackf16((uint32_t)w)), a01);
        a23 = ffma2(vv, packf2(unpackf16((uint32_t)(w >> 32))), a23);
    }

    float2 p01 = unpack2(a01), p23 = unpack2(a23);
    float4 b = ((const float4*)b1)[lane];
    float4 r;
    r.x = fmaxf(p01.x + b.x, 0.f);
    r.y = fmaxf(p01.y + b.y, 0.f);
    r.z = fmaxf(p23.x + b.z, 0.f);
    r.w = fmaxf(p23.y + b.w, 0.f);
    uint2 pv;
    pv.x = packf16(make_float2(r.x, r.y));
    pv.y = packf16(make_float2(r.z, r.w));
    *(uint2*)((char*)g_hh + (size_t)warp * 256 + lane * 8) = pv;
}

// ---------------- GEMM2: s2h = fp16(h @ W2) (fp16 h stream, BM=256, BK=8, 2-stage) ----------------
#define G2_BM 256
#define G2_BK 8
#define G2_NT (NHID / G2_BK)     // 16
__global__ void __launch_bounds__(256) gemm2_kernel(const float* __restrict__ W2) {
    __shared__ uint32_t Hs[2][G2_BM * 4];     // 2 stages x 256 rows x 8 fp16 (4KB each)
    __shared__ float2   Wp[NHID * 20];        // 20 KB

    const int tid = threadIdx.x;
    const int pg  = tid & 3;
    const int rg  = tid >> 2;
    const int row0 = blockIdx.x * G2_BM;

    for (int j = tid; j < NHID * 20; j += 256) {
        int k = j / 20, p = j % 20;
        Wp[j] = *(const float2*)&W2[k * NCLASS + 2 * p];
    }

    unsigned hsb = (unsigned)__cvta_generic_to_shared(&Hs[0][0]);

#define G2_PREFETCH(stage, k0)                                                     \
    do {                                                                           \
        int grow = row0 + tid;                                                     \
        cpa16(hsb + (stage) * 4096 + tid * 16,                                     \
              (const char*)g_hh + (size_t)grow * 256 + (k0) * 2, grow < NN);       \
        cpa_commit();                                                              \
    } while (0)

    G2_PREFETCH(0, 0);

    unsigned long long acc[4][5];
#pragma unroll
    for (int i = 0; i < 4; i++)
#pragma unroll
        for (int j = 0; j < 5; j++) acc[i][j] = 0ull;

    for (int t = 0; t < G2_NT; t++) {
        if (t + 1 < G2_NT) {
            G2_PREFETCH((t + 1) & 1, (t + 1) * G2_BK);
            cpa_wait1();
        } else {
            cpa_wait0();
        }
        __syncthreads();

        const int st = t & 1;
        const int kbase = t * G2_BK;
#pragma unroll
        for (int kp = 0; kp < 4; kp++) {
            float2 hf[4];
#pragma unroll
            for (int i = 0; i < 4; i++)
                hf[i] = unpackf16(Hs[st][(rg + 64 * i) * 4 + kp]);
#pragma unroll
            for (int half = 0; half < 2; half++) {
                int kk = kbase + 2 * kp + half;
                unsigned long long wv[5];
#pragma unroll
                for (int j = 0; j < 5; j++)
                    wv[j] = *(const unsigned long long*)&Wp[kk * 20 + pg * 5 + j];
                unsigned long long hd[4];
#pragma unroll
                for (int i = 0; i < 4; i++)
                    hd[i] = dup2(half ? hf[i].y : hf[i].x);
#pragma unroll
                for (int i = 0; i < 4; i++)
#pragma unroll
                    for (int j = 0; j < 5; j++)
                        acc[i][j] = ffma2(hd[i], wv[j], acc[i][j]);
            }
        }
        __syncthreads();
    }

#pragma unroll
    for (int i = 0; i < 4; i++) {
        int grow = row0 + rg + 64 * i;
        if (grow < NN) {
#pragma unroll
            for (int j = 0; j < 5; j++) {
                float2 v = unpack2(acc[i][j]);
                *(uint32_t*)((char*)g_s2h + (size_t)grow * 80 + (pg * 5 + j) * 4) = packf16(v);
            }
        }
    }
#undef G2_PREFETCH
}

// ---------------- SpMM2 + bias + log_softmax (fp16 gathers, 3 slots x 2-deep) ----------------
__global__ void spmm2_lsm_kernel(const int* __restrict__ acol, const float* __restrict__ aval,
                                 const float* __restrict__ b2, float* __restrict__ out) {
    int warp = (blockIdx.x * blockDim.x + threadIdx.x) >> 5;
    int lane = threadIdx.x & 31;
    if (warp >= NN) return;

    int s = g_rowptr[warp];
    int e = g_rowptr[warp + 1];

    const int slot = lane / 10;          // 0,1,2 (lanes 30,31 inactive)
    const int seg  = lane - slot * 10;   // 0..9
    const bool lact = lane < 30;

    const char* S2b = (const char*)g_s2h + (size_t)seg * 8;   // row stride 80B
    unsigned long long acc0 = 0ull, acc1 = 0ull;

    int i = s;
    for (; i + 5 < e; i += 6) {
        int ei0 = i + slot, ei1 = i + 3 + slot;
        int c0 = 0, c1 = 0;
        float v0 = 0.f, v1 = 0.f;
        unsigned long long wa = 0ull, wb = 0ull;
        if (lact) {
            c0 = __ldcs(&acol[ei0]);
            c1 = __ldcs(&acol[ei1]);
            v0 = __ldcs(&aval[ei0]);
            v1 = __ldcs(&aval[ei1]);
            wa = ldg64cg(S2b + (size_t)c0 * 80);
            wb = ldg64cg(S2b + (size_t)c1 * 80);
        }
        unsigned long long vv0 = dup2(v0), vv1 = dup2(v1);
        acc0 = ffma2(vv0, packf2(unpackf16((uint32_t)wa)), acc0);
        acc1 = ffma2(vv0, packf2(unpackf16((uint32_t)(wa >> 32))), acc1);
        acc0 = ffma2(vv1, packf2(unpackf16((uint32_t)wb)), acc0);
        acc1 = ffma2(vv1, packf2(unpackf16((uint32_t)(wb >> 32))), acc1);
    }
    for (; i < e; i += 3) {
        int ei = i + slot;
        bool ok = lact && (ei < e);
        int   c = 0;
        float v = 0.f;
        unsigned long long w = 0ull;
        if (ok) {
            c = __ldcs(&acol[ei]);
            v = __ldcs(&aval[ei]);
            w = ldg64cg(S2b + (size_t)c * 80);
        }
        unsigned long long vv = dup2(v);
        acc0 = ffma2(vv, packf2(unpackf16((uint32_t)w)), acc0);
        acc1 = ffma2(vv, packf2(unpackf16((uint32_t)(w >> 32))), acc1);
    }

    float2 a0 = unpack2(acc0), a1 = unpack2(acc1);
    float vals[4] = {a0.x, a0.y, a1.x, a1.y};
#pragma unroll
    for (int j = 0; j < 4; j++) {
        float v10 = __shfl_down_sync(0xFFFFFFFFu, vals[j], 10);
        float v20 = __shfl_down_sync(0xFFFFFFFFu, vals[j], 20);
        vals[j] = vals[j] + v10 + v20;
    }

    bool outl = lane < 10;
    if (outl) {
        float4 bb = __ldg((const float4*)&b2[4 * seg]);
        vals[0] += bb.x; vals[1] += bb.y; vals[2] += bb.z; vals[3] += bb.w;
    }

    float m = outl ? fmaxf(fmaxf(vals[0], vals[1]), fmaxf(vals[2], vals[3])) : -INFINITY;
#pragma unroll
    for (int off = 16; off > 0; off >>= 1)
        m = fmaxf(m, __shfl_xor_sync(0xFFFFFFFFu, m, off));

    float se = outl ? (expf(vals[0] - m) + expf(vals[1] - m) +
                       expf(vals[2] - m) + expf(vals[3] - m)) : 0.f;
#pragma unroll
    for (int off = 16; off > 0; off >>= 1)
        se += __shfl_xor_sync(0xFFFFFFFFu, se, off);

    float lse = m + logf(se);
    if (outl) {
        float4 o;
        o.x = vals[0] - lse; o.y = vals[1] - lse;
        o.z = vals[2] - lse; o.w = vals[3] - lse;
        *(float4*)&out[(size_t)warp * NCLASS + 4 * seg] = o;
    }
}

// ---------------- launch ----------------
extern "C" void kernel_launch(void* const* d_in, const int* in_sizes, int n_in,
                              void* d_out, int out_size) {
    const float* x    = (const float*)d_in[0];
    const int*   arow = (const int*)  d_in[1];
    const int*   acol = (const int*)  d_in[2];
    const float* aval = (const float*)d_in[3];
    // d_in[4] = i (unused)
    const float* W1 = (const float*)d_in[5];
    const float* b1 = (const float*)d_in[6];
    const float* W2 = (const float*)d_in[7];
    const float* b2 = (const float*)d_in[8];
    float* out = (float*)d_out;

    build_rowptr_kernel<<<(NN + 1 + 255) / 256, 256>>>(arow);
    w1bf16_kernel<<<(NFEAT * NHID + 255) / 256, 256>>>(W1);
    gemm1_bf16_kernel<<<(NN + 127) / 128, 512>>>(x);
    spmm1_kernel<<<(NN * 32 + 255) / 256, 256>>>(acol, aval, b1);
    gemm2_kernel<<<(NN + G2_BM - 1) / G2_BM, 256>>>(W2);
    spmm2_lsm_kernel<<<(NN * 32 + 255) / 256, 256>>>(acol, aval, b2, out);
}

// round 16
// speedup vs baseline: 1.0363x; 1.0363x over previous
#include <cuda_runtime.h>
#include <math.h>
#include <cstdint>

#define NN    100000
#define EE    3200000
#define NFEAT 256
#define NHID  128
#define NCLASS 40

// ---------------- scratch ----------------
__device__ __align__(16) unsigned short g_s1h[NN * NHID];   // x @ W1, fp16 (25.6 MB)
__device__ __align__(16) unsigned short g_hh [NN * NHID];   // relu(A@s1+b1), fp16 (25.6 MB)
__device__ __align__(16) unsigned short g_s2h[NN * NCLASS]; // h @ W2, fp16 (8 MB)
__device__ int g_rowptr[NN + 1];
// W1 bf16 hi/lo fragment image for m16n8k16
__device__ __align__(16) uint32_t g_Bbf[32768];             // 128 KB

// ---------------- f32x2 packed helpers ----------------
__device__ __forceinline__ unsigned long long ffma2(unsigned long long a,
                                                    unsigned long long b,
                                                    unsigned long long c) {
    unsigned long long d;
    asm("fma.rn.f32x2 %0, %1, %2, %3;" : "=l"(d) : "l"(a), "l"(b), "l"(c));
    return d;
}
__device__ __forceinline__ unsigned long long dup2(float a) {
    unsigned long long d;
    asm("mov.b64 %0, {%1, %1};" : "=l"(d) : "f"(a));
    return d;
}
__device__ __forceinline__ unsigned long long packf2(float2 f) {
    unsigned long long d;
    asm("mov.b64 %0, {%1, %2};" : "=l"(d) : "f"(f.x), "f"(f.y));
    return d;
}
__device__ __forceinline__ float2 unpack2(unsigned long long v) {
    float2 f;
    asm("mov.b64 {%0, %1}, %2;" : "=f"(f.x), "=f"(f.y) : "l"(v));
    return f;
}
__device__ __forceinline__ unsigned long long ldg64cg(const void* p) {
    unsigned long long v;
    asm volatile("ld.global.cg.b64 %0, [%1];" : "=l"(v) : "l"(p));
    return v;
}

// ---------------- fp16 storage helpers ----------------
__device__ __forceinline__ uint32_t packf16(float2 v) {      // low16 = f16(v.x)
    uint32_t d;
    asm("cvt.rn.f16x2.f32 %0, %1, %2;" : "=r"(d) : "f"(v.y), "f"(v.x));
    return d;
}
__device__ __forceinline__ float2 unpackf16(uint32_t h) {
    float2 f;
    asm("{\n\t.reg .b16 lo, hi;\n\t"
        "mov.b32 {lo, hi}, %2;\n\t"
        "cvt.f32.f16 %0, lo;\n\t"
        "cvt.f32.f16 %1, hi;\n\t}"
        : "=f"(f.x), "=f"(f.y) : "r"(h));
    return f;
}

// ---------------- cp.async helpers ----------------
__device__ __forceinline__ void cpa16(unsigned dst, const void* src, bool pred) {
    int sz = pred ? 16 : 0;
    asm volatile("cp.async.ca.shared.global [%0], [%1], 16, %2;\n"
                 :: "r"(dst), "l"(src), "r"(sz));
}
__device__ __forceinline__ void cpa_commit() { asm volatile("cp.async.commit_group;\n"); }
__device__ __forceinline__ void cpa_wait1()  { asm volatile("cp.async.wait_group 1;\n"); }
__device__ __forceinline__ void cpa_wait0()  { asm volatile("cp.async.wait_group 0;\n"); }

// ---------------- bf16 helpers (gemm1 hi/lo split) ----------------
__device__ __forceinline__ uint32_t pack2bf(float2 v) {
    uint32_t d;
    asm("cvt.rn.bf16x2.f32 %0, %1, %2;" : "=r"(d) : "f"(v.y), "f"(v.x));
    return d;
}
__device__ __forceinline__ uint32_t pack2bf_lo(float2 v, uint32_t h) {
    float fx = __uint_as_float(h << 16);
    float fy = __uint_as_float(h & 0xFFFF0000u);
    float2 r = make_float2(v.x - fx, v.y - fy);
    return pack2bf(r);
}
#define MMA_BF16(d, a0, a1, a2, a3, b0, b1)                                      \
    asm volatile("mma.sync.aligned.m16n8k16.row.col.f32.bf16.bf16.f32 "         \
        "{%0,%1,%2,%3}, {%4,%5,%6,%7}, {%8,%9}, {%0,%1,%2,%3};"                 \
        : "+f"((d)[0]), "+f"((d)[1]), "+f"((d)[2]), "+f"((d)[3])                \
        : "r"(a0), "r"(a1), "r"(a2), "r"(a3), "r"(b0), "r"(b1))

// ---------------- CSR row_ptr ----------------
__global__ void build_rowptr_kernel(const int* __restrict__ arow) {
    int r = blockIdx.x * blockDim.x + threadIdx.x;
    if (r > NN) return;
    int lo = 0, hi = EE;
    while (lo < hi) {
        int mid = (lo + hi) >> 1;
        if (arow[mid] < r) lo = mid + 1; else hi = mid;
    }
    g_rowptr[r] = lo;
}

// ---------------- W1 -> bf16 hi/lo fragment image (m16n8k16, col-major B) ----------------
__global__ void w1bf16_kernel(const float* __restrict__ W1) {
    int idx = blockIdx.x * blockDim.x + threadIdx.x;
    if (idx >= NFEAT * NHID) return;
    int k = idx >> 7, n = idx & 127;
    float w = W1[idx];
    uint32_t hp = pack2bf(make_float2(w, 0.f));
    unsigned short hi16 = (unsigned short)(hp & 0xFFFFu);
    float fh = __uint_as_float((uint32_t)hi16 << 16);
    uint32_t lp = pack2bf(make_float2(w - fh, 0.f));
    unsigned short lo16 = (unsigned short)(lp & 0xFFFFu);

    int c16 = k >> 4, kk = k & 15;
    int ct = n >> 3, gid = n & 7;
    int reg = kk >> 3;
    int tig = (kk & 7) >> 1;
    int pos = kk & 1;
    int lane = gid * 4 + tig;
    int base16 = ((((c16 * 16 + ct) * 2 + 0) * 32 + lane) * 2 + reg) * 2 + pos;
    unsigned short* B16 = (unsigned short*)g_Bbf;
    B16[base16]       = hi16;     // h = 0
    B16[base16 + 128] = lo16;     // h = 1
}

// ---------------- GEMM1 (mma.sync bf16 hi/lo): g_s1h = fp16(X @ W1) ----------------
__global__ void __launch_bounds__(512) gemm1_bf16_kernel(const float* __restrict__ X) {
    __shared__ __align__(16) uint32_t sB[2][4096];   // 2 x 16KB

    const int tid  = threadIdx.x;
    const int lane = tid & 31;
    const int warp = tid >> 5;
    const int wrow = (warp >> 1) * 16;
    const int wcol = (warp & 1) * 64;
    const int row0 = blockIdx.x * 128;
    const int gid  = lane >> 2;
    const int tig  = lane & 3;
    const int ctb  = wcol >> 3;

    unsigned sb_addr = (unsigned)__cvta_generic_to_shared(&sB[0][0]);

    int rowi[2];
    bool rokg[2];
#pragma unroll
    for (int p = 0; p < 2; p++) {
        rowi[p] = row0 + wrow + gid + p * 8;
        rokg[p] = rowi[p] < NN;
    }

    float acc[8][4];
#pragma unroll
    for (int c = 0; c < 8; c++)
#pragma unroll
        for (int j = 0; j < 4; j++) acc[c][j] = 0.f;

#define G1_PREFETCH(stage, s)                                                    \
    do {                                                                         \
        _Pragma("unroll")                                                        \
        for (int j = 0; j < 2; j++) {                                            \
            int off = (j * 512 + tid) * 16;                                      \
            cpa16(sb_addr + (stage) * 16384 + off,                               \
                  (const char*)g_Bbf + (s) * 16384 + off, true);                 \
        }                                                                        \
        cpa_commit();                                                            \
    } while (0)

#define G1_LOAD_A(dst, s_)                                                       \
    do {                                                                         \
        _Pragma("unroll")                                                        \
        for (int sub = 0; sub < 2; sub++)                                        \
            _Pragma("unroll")                                                    \
            for (int p = 0; p < 2; p++)                                          \
                _Pragma("unroll")                                                \
                for (int q = 0; q < 2; q++) {                                    \
                    int kidx = (s_) * 32 + sub * 16 + tig * 2 + q * 8;           \
                    (dst)[sub][p][q] = rokg[p]                                   \
                        ? __ldg((const float2*)&X[(size_t)rowi[p] * NFEAT + kidx]) \
                        : make_float2(0.f, 0.f);                                 \
                }                                                                \
    } while (0)

    float2 srcA[2][2][2], srcB[2][2][2];
    G1_LOAD_A(srcA, 0);
    G1_PREFETCH(0, 0);

    for (int s = 0; s < 8; s++) {
        if (s + 1 < 8) {
            G1_PREFETCH((s + 1) & 1, s + 1);
            if (s & 1) G1_LOAD_A(srcA, s + 1); else G1_LOAD_A(srcB, s + 1);
            cpa_wait1();
        } else {
            cpa_wait0();
        }
        __syncthreads();

        float2 (*cur)[2][2] = (s & 1) ? srcB : srcA;
        const uint2* Bst = (const uint2*)&sB[s & 1][0];
#pragma unroll
        for (int sub = 0; sub < 2; sub++) {
            uint32_t ah[4], al[4];
            ah[0] = pack2bf(cur[sub][0][0]);
            ah[1] = pack2bf(cur[sub][1][0]);
            ah[2] = pack2bf(cur[sub][0][1]);
            ah[3] = pack2bf(cur[sub][1][1]);
            al[0] = pack2bf_lo(cur[sub][0][0], ah[0]);
            al[1] = pack2bf_lo(cur[sub][1][0], ah[1]);
            al[2] = pack2bf_lo(cur[sub][0][1], ah[2]);
            al[3] = pack2bf_lo(cur[sub][1][1], ah[3]);
#pragma unroll
            for (int c = 0; c < 8; c++) {
                int ctg = ctb + c;
                uint2 bhi = Bst[sub * 1024 + (ctg * 2 + 0) * 32 + lane];
                uint2 blo = Bst[sub * 1024 + (ctg * 2 + 1) * 32 + lane];
                MMA_BF16(acc[c], ah[0], ah[1], ah[2], ah[3], bhi.x, bhi.y);
                MMA_BF16(acc[c], ah[0], ah[1], ah[2], ah[3], blo.x, blo.y);
                MMA_BF16(acc[c], al[0], al[1], al[2], al[3], bhi.x, bhi.y);
            }
        }
        __syncthreads();
    }

#pragma unroll
    for (int c = 0; c < 8; c++) {
        int col = wcol + c * 8 + tig * 2;
        if (rokg[0])
            *(uint32_t*)&g_s1h[(size_t)rowi[0] * NHID + col] =
                packf16(make_float2(acc[c][0], acc[c][1]));
        if (rokg[1])
            *(uint32_t*)&g_s1h[(size_t)rowi[1] * NHID + col] =
                packf16(make_float2(acc[c][2], acc[c][3]));
    }
#undef G1_PREFETCH
#undef G1_LOAD_A
}

// ---------------- SpMM1 + bias + ReLU (R14 form: warp/row, fp16 gathers, 2-edge) ----------------
__global__ void spmm1_kernel(const int* __restrict__ acol, const float* __restrict__ aval,
                             const float* __restrict__ b1) {
    int warp = (blockIdx.x * blockDim.x + threadIdx.x) >> 5;
    int lane = threadIdx.x & 31;
    if (warp >= NN) return;

    int s = g_rowptr[warp];
    int e = g_rowptr[warp + 1];

    const char* S1b = (const char*)g_s1h + (size_t)lane * 8;   // row stride 256B
    unsigned long long a01 = 0ull, a23 = 0ull;

    int i = s;
    if ((i & 1) && i < e) {
        int   c = __ldcs(&acol[i]);
        float v = __ldcs(&aval[i]);
        unsigned long long w = ldg64cg(S1b + (size_t)c * 256);
        unsigned long long vv = dup2(v);
        a01 = ffma2(vv, packf2(unpackf16((uint32_t)w)), a01);
        a23 = ffma2(vv, packf2(unpackf16((uint32_t)(w >> 32))), a23);
        i++;
    }
    for (; i + 1 < e; i += 2) {
        int2   c2 = __ldcs((const int2*)&acol[i]);
        float2 v2 = __ldcs((const float2*)&aval[i]);
        unsigned long long w0 = ldg64cg(S1b + (size_t)c2.x * 256);
        unsigned long long w1 = ldg64cg(S1b + (size_t)c2.y * 256);
        unsigned long long vx = dup2(v2.x), vy = dup2(v2.y);
        a01 = ffma2(vx, packf2(unpackf16((uint32_t)w0)), a01);
        a23 = ffma2(vx, packf2(unpackf16((uint32_t)(w0 >> 32))), a23);
        a01 = ffma2(vy, packf2(unpackf16((uint32_t)w1)), a01);
        a23 = ffma2(vy, packf2(unpackf16((uint32_t)(w1 >> 32))), a23);
    }
    if (i < e) {
        int   c = __ldcs(&acol[i]);
        float v = __ldcs(&aval[i]);
        unsigned long long w = ldg64cg(S1b + (size_t)c * 256);
        unsigned long long vv = dup2(v);
        a01 = ffma2(vv, packf2(unpackf16((uint32_t)w)), a01);
        a23 = ffma2(vv, packf2(unpackf16((uint32_t)(w >> 32))), a23);
    }

    float2 p01 = unpack2(a01), p23 = unpack2(a23);
    float4 b = ((const float4*)b1)[lane];
    float4 r;
    r.x = fmaxf(p01.x + b.x, 0.f);
    r.y = fmaxf(p01.y + b.y, 0.f);
    r.z = fmaxf(p23.x + b.z, 0.f);
    r.w = fmaxf(p23.y + b.w, 0.f);
    uint2 pv;
    pv.x = packf16(make_float2(r.x, r.y));
    pv.y = packf16(make_float2(r.z, r.w));
    *(uint2*)((char*)g_hh + (size_t)warp * 256 + lane * 8) = pv;
}

// ---------------- GEMM2: s2h = fp16(h @ W2) (fp16 h stream, BM=256, BK=8, 2-stage) ----------------
#define G2_BM 256
#define G2_BK 8
#define G2_NT (NHID / G2_BK)     // 16
__global__ void __launch_bounds__(256) gemm2_kernel(const float* __restrict__ W2) {
    __shared__ uint32_t Hs[2][G2_BM * 4];     // 2 stages x 256 rows x 8 fp16 (4KB each)
    __shared__ float2   Wp[NHID * 20];        // 20 KB

    const int tid = threadIdx.x;
    const int pg  = tid & 3;
    const int rg  = tid >> 2;
    const int row0 = blockIdx.x * G2_BM;

    for (int j = tid; j < NHID * 20; j += 256) {
        int k = j / 20, p = j % 20;
        Wp[j] = *(const float2*)&W2[k * NCLASS + 2 * p];
    }

    unsigned hsb = (unsigned)__cvta_generic_to_shared(&Hs[0][0]);

#define G2_PREFETCH(stage, k0)                                                     \
    do {                                                                           \
        int grow = row0 + tid;                                                     \
        cpa16(hsb + (stage) * 4096 + tid * 16,                                     \
              (const char*)g_hh + (size_t)grow * 256 + (k0) * 2, grow < NN);       \
        cpa_commit();                                                              \
    } while (0)

    G2_PREFETCH(0, 0);

    unsigned long long acc[4][5];
#pragma unroll
    for (int i = 0; i < 4; i++)
#pragma unroll
        for (int j = 0; j < 5; j++) acc[i][j] = 0ull;

    for (int t = 0; t < G2_NT; t++) {
        if (t + 1 < G2_NT) {
            G2_PREFETCH((t + 1) & 1, (t + 1) * G2_BK);
            cpa_wait1();
        } else {
            cpa_wait0();
        }
        __syncthreads();

        const int st = t & 1;
        const int kbase = t * G2_BK;
#pragma unroll
        for (int kp = 0; kp < 4; kp++) {
            float2 hf[4];
#pragma unroll
            for (int i = 0; i < 4; i++)
                hf[i] = unpackf16(Hs[st][(rg + 64 * i) * 4 + kp]);
#pragma unroll
            for (int half = 0; half < 2; half++) {
                int kk = kbase + 2 * kp + half;
                unsigned long long wv[5];
#pragma unroll
                for (int j = 0; j < 5; j++)
                    wv[j] = *(const unsigned long long*)&Wp[kk * 20 + pg * 5 + j];
                unsigned long long hd[4];
#pragma unroll
                for (int i = 0; i < 4; i++)
                    hd[i] = dup2(half ? hf[i].y : hf[i].x);
#pragma unroll
                for (int i = 0; i < 4; i++)
#pragma unroll
                    for (int j = 0; j < 5; j++)
                        acc[i][j] = ffma2(hd[i], wv[j], acc[i][j]);
            }
        }
        __syncthreads();
    }

#pragma unroll
    for (int i = 0; i < 4; i++) {
        int grow = row0 + rg + 64 * i;
        if (grow < NN) {
#pragma unroll
            for (int j = 0; j < 5; j++) {
                float2 v = unpack2(acc[i][j]);
                *(uint32_t*)((char*)g_s2h + (size_t)grow * 80 + (pg * 5 + j) * 4) = packf16(v);
            }
        }
    }
#undef G2_PREFETCH
}

// ---------------- SpMM2 + bias + log_softmax (fp16 gathers, 3 slots x 2-deep) ----------------
__global__ void spmm2_lsm_kernel(const int* __restrict__ acol, const float* __restrict__ aval,
                                 const float* __restrict__ b2, float* __restrict__ out) {
    int warp = (blockIdx.x * blockDim.x + threadIdx.x) >> 5;
    int lane = threadIdx.x & 31;
    if (warp >= NN) return;

    int s = g_rowptr[warp];
    int e = g_rowptr[warp + 1];

    const int slot = lane / 10;          // 0,1,2 (lanes 30,31 inactive)
    const int seg  = lane - slot * 10;   // 0..9
    const bool lact = lane < 30;

    const char* S2b = (const char*)g_s2h + (size_t)seg * 8;   // row stride 80B
    unsigned long long acc0 = 0ull, acc1 = 0ull;

    int i = s;
    for (; i + 5 < e; i += 6) {
        int ei0 = i + slot, ei1 = i + 3 + slot;
        int c0 = 0, c1 = 0;
        float v0 = 0.f, v1 = 0.f;
        unsigned long long wa = 0ull, wb = 0ull;
        if (lact) {
            c0 = __ldcs(&acol[ei0]);
            c1 = __ldcs(&acol[ei1]);
            v0 = __ldcs(&aval[ei0]);
            v1 = __ldcs(&aval[ei1]);
            wa = ldg64cg(S2b + (size_t)c0 * 80);
            wb = ldg64cg(S2b + (size_t)c1 * 80);
        }
        unsigned long long vv0 = dup2(v0), vv1 = dup2(v1);
        acc0 = ffma2(vv0, packf2(unpackf16((uint32_t)wa)), acc0);
        acc1 = ffma2(vv0, packf2(unpackf16((uint32_t)(wa >> 32))), acc1);
        acc0 = ffma2(vv1, packf2(unpackf16((uint32_t)wb)), acc0);
        acc1 = ffma2(vv1, packf2(unpackf16((uint32_t)(wb >> 32))), acc1);
    }
    for (; i < e; i += 3) {
        int ei = i + slot;
        bool ok = lact && (ei < e);
        int   c = 0;
        float v = 0.f;
        unsigned long long w = 0ull;
        if (ok) {
            c = __ldcs(&acol[ei]);
            v = __ldcs(&aval[ei]);
            w = ldg64cg(S2b + (size_t)c * 80);
        }
        unsigned long long vv = dup2(v);
        acc0 = ffma2(vv, packf2(unpackf16((uint32_t)w)), acc0);
        acc1 = ffma2(vv, packf2(unpackf16((uint32_t)(w >> 32))), acc1);
    }

    float2 a0 = unpack2(acc0), a1 = unpack2(acc1);
    float vals[4] = {a0.x, a0.y, a1.x, a1.y};
#pragma unroll
    for (int j = 0; j < 4; j++) {
        float v10 = __shfl_down_sync(0xFFFFFFFFu, vals[j], 10);
        float v20 = __shfl_down_sync(0xFFFFFFFFu, vals[j], 20);
        vals[j] = vals[j] + v10 + v20;
    }

    bool outl = lane < 10;
    if (outl) {
        float4 bb = __ldg((const float4*)&b2[4 * seg]);
        vals[0] += bb.x; vals[1] += bb.y; vals[2] += bb.z; vals[3] += bb.w;
    }

    float m = outl ? fmaxf(fmaxf(vals[0], vals[1]), fmaxf(vals[2], vals[3])) : -INFINITY;
#pragma unroll
    for (int off = 16; off > 0; off >>= 1)
        m = fmaxf(m, __shfl_xor_sync(0xFFFFFFFFu, m, off));

    float se = outl ? (expf(vals[0] - m) + expf(vals[1] - m) +
                       expf(vals[2] - m) + expf(vals[3] - m)) : 0.f;
#pragma unroll
    for (int off = 16; off > 0; off >>= 1)
        se += __shfl_xor_sync(0xFFFFFFFFu, se, off);

    float lse = m + logf(se);
    if (outl) {
        float4 o;
        o.x = vals[0] - lse; o.y = vals[1] - lse;
        o.z = vals[2] - lse; o.w = vals[3] - lse;
        *(float4*)&out[(size_t)warp * NCLASS + 4 * seg] = o;
    }
}

// ---------------- launch ----------------
extern "C" void kernel_launch(void* const* d_in, const int* in_sizes, int n_in,
                              void* d_out, int out_size) {
    const float* x    = (const float*)d_in[0];
    const int*   arow = (const int*)  d_in[1];
    const int*   acol = (const int*)  d_in[2];
    const float* aval = (const float*)d_in[3];
    // d_in[4] = i (unused)
    const float* W1 = (const float*)d_in[5];
    const float* b1 = (const float*)d_in[6];
    const float* W2 = (const float*)d_in[7];
    const float* b2 = (const float*)d_in[8];
    float* out = (float*)d_out;

    build_rowptr_kernel<<<(NN + 1 + 255) / 256, 256>>>(arow);
    w1bf16_kernel<<<(NFEAT * NHID + 255) / 256, 256>>>(W1);
    gemm1_bf16_kernel<<<(NN + 127) / 128, 512>>>(x);
    spmm1_kernel<<<(NN * 32 + 255) / 256, 256>>>(acol, aval, b1);
    gemm2_kernel<<<(NN + G2_BM - 1) / G2_BM, 256>>>(W2);
    spmm2_lsm_kernel<<<(NN * 32 + 255) / 256, 256>>>(acol, aval, b2, out);
}

// round 17
// speedup vs baseline: 1.1540x; 1.1136x over previous
#include <cuda_runtime.h>
#include <math.h>
#include <cstdint>

#define NN    100000
#define EE    3200000
#define NFEAT 256
#define NHID  128
#define NCLASS 40

// ---------------- scratch ----------------
__device__ __align__(16) unsigned short g_s1h[NN * NHID];   // x @ W1, fp16 (25.6 MB)
__device__ __align__(16) unsigned short g_hh [NN * NHID];   // relu(A@s1+b1), fp16 (25.6 MB)
__device__ __align__(16) unsigned short g_s2h[NN * NCLASS]; // h @ W2, fp16 (8 MB)
__device__ int g_rowptr[NN + 1];
// W1 fp16 fragment image for m16n8k16: [c16(16)][ct(16)][lane(32)][reg(2)][pos(2)] u16
__device__ __align__(16) uint32_t g_Bh[16384];              // 64 KB

// ---------------- f32x2 packed helpers ----------------
__device__ __forceinline__ unsigned long long ffma2(unsigned long long a,
                                                    unsigned long long b,
                                                    unsigned long long c) {
    unsigned long long d;
    asm("fma.rn.f32x2 %0, %1, %2, %3;" : "=l"(d) : "l"(a), "l"(b), "l"(c));
    return d;
}
__device__ __forceinline__ unsigned long long dup2(float a) {
    unsigned long long d;
    asm("mov.b64 %0, {%1, %1};" : "=l"(d) : "f"(a));
    return d;
}
__device__ __forceinline__ unsigned long long packf2(float2 f) {
    unsigned long long d;
    asm("mov.b64 %0, {%1, %2};" : "=l"(d) : "f"(f.x), "f"(f.y));
    return d;
}
__device__ __forceinline__ float2 unpack2(unsigned long long v) {
    float2 f;
    asm("mov.b64 {%0, %1}, %2;" : "=f"(f.x), "=f"(f.y) : "l"(v));
    return f;
}
__device__ __forceinline__ unsigned long long ldg64cg(const void* p) {
    unsigned long long v;
    asm volatile("ld.global.cg.b64 %0, [%1];" : "=l"(v) : "l"(p));
    return v;
}

// ---------------- fp16 helpers ----------------
__device__ __forceinline__ uint32_t packf16(float2 v) {      // low16 = f16(v.x)
    uint32_t d;
    asm("cvt.rn.f16x2.f32 %0, %1, %2;" : "=r"(d) : "f"(v.y), "f"(v.x));
    return d;
}
__device__ __forceinline__ float2 unpackf16(uint32_t h) {
    float2 f;
    asm("{\n\t.reg .b16 lo, hi;\n\t"
        "mov.b32 {lo, hi}, %2;\n\t"
        "cvt.f32.f16 %0, lo;\n\t"
        "cvt.f32.f16 %1, hi;\n\t}"
        : "=f"(f.x), "=f"(f.y) : "r"(h));
    return f;
}
#define MMA_F16(d, a0, a1, a2, a3, b0, b1)                                       \
    asm volatile("mma.sync.aligned.m16n8k16.row.col.f32.f16.f16.f32 "           \
        "{%0,%1,%2,%3}, {%4,%5,%6,%7}, {%8,%9}, {%0,%1,%2,%3};"                 \
        : "+f"((d)[0]), "+f"((d)[1]), "+f"((d)[2]), "+f"((d)[3])                \
        : "r"(a0), "r"(a1), "r"(a2), "r"(a3), "r"(b0), "r"(b1))

// ---------------- cp.async helpers ----------------
__device__ __forceinline__ void cpa16(unsigned dst, const void* src, bool pred) {
    int sz = pred ? 16 : 0;
    asm volatile("cp.async.ca.shared.global [%0], [%1], 16, %2;\n"
                 :: "r"(dst), "l"(src), "r"(sz));
}
__device__ __forceinline__ void cpa_commit() { asm volatile("cp.async.commit_group;\n"); }
__device__ __forceinline__ void cpa_wait1()  { asm volatile("cp.async.wait_group 1;\n"); }
__device__ __forceinline__ void cpa_wait0()  { asm volatile("cp.async.wait_group 0;\n"); }

// ---------------- CSR row_ptr ----------------
__global__ void build_rowptr_kernel(const int* __restrict__ arow) {
    int r = blockIdx.x * blockDim.x + threadIdx.x;
    if (r > NN) return;
    int lo = 0, hi = EE;
    while (lo < hi) {
        int mid = (lo + hi) >> 1;
        if (arow[mid] < r) lo = mid + 1; else hi = mid;
    }
    g_rowptr[r] = lo;
}

// ---------------- W1 -> fp16 fragment image (m16n8k16, col-major B) ----------------
__global__ void w1f16_kernel(const float* __restrict__ W1) {
    int idx = blockIdx.x * blockDim.x + threadIdx.x;
    if (idx >= NFEAT * NHID) return;
    int k = idx >> 7, n = idx & 127;
    float w = W1[idx];
    uint32_t hp = packf16(make_float2(w, 0.f));
    unsigned short h16 = (unsigned short)(hp & 0xFFFFu);

    int c16 = k >> 4, kk = k & 15;
    int ct = n >> 3, gid = n & 7;
    int reg = kk >> 3;
    int tig = (kk & 7) >> 1;
    int pos = kk & 1;
    int lane = gid * 4 + tig;
    int base16 = ((((c16 * 16 + ct) * 32 + lane) * 2 + reg)) * 2 + pos;
    ((unsigned short*)g_Bh)[base16] = h16;
}

// ---------------- GEMM1 (mma.sync fp16 single-pass): g_s1h = fp16(X @ W1) ----------------
// 128x128 tile/CTA, 512 threads, 16 warps in 8x2 (16 rows x 64 cols each).
// Stage = 32 k (2 k16 sub-chunks); B stage 8KB cp.async double-buffered; A frags
// double-buffered in regs (loaded a stage ahead).
__global__ void __launch_bounds__(512) gemm1_f16_kernel(const float* __restrict__ X) {
    __shared__ __align__(16) uint32_t sB[2][2048];   // 2 x 8KB

    const int tid  = threadIdx.x;
    const int lane = tid & 31;
    const int warp = tid >> 5;
    const int wrow = (warp >> 1) * 16;
    const int wcol = (warp & 1) * 64;
    const int row0 = blockIdx.x * 128;
    const int gid  = lane >> 2;
    const int tig  = lane & 3;
    const int ctb  = wcol >> 3;

    unsigned sb_addr = (unsigned)__cvta_generic_to_shared(&sB[0][0]);

    int rowi[2];
    bool rokg[2];
#pragma unroll
    for (int p = 0; p < 2; p++) {
        rowi[p] = row0 + wrow + gid + p * 8;
        rokg[p] = rowi[p] < NN;
    }

    float acc[8][4];
#pragma unroll
    for (int c = 0; c < 8; c++)
#pragma unroll
        for (int j = 0; j < 4; j++) acc[c][j] = 0.f;

    // per stage: 8KB = 512 x 16B -> 1 cpa16 per thread
#define G1_PREFETCH(stage, s)                                                    \
    do {                                                                         \
        cpa16(sb_addr + (stage) * 8192 + tid * 16,                               \
              (const char*)g_Bh + (s) * 8192 + tid * 16, true);                  \
        cpa_commit();                                                            \
    } while (0)

#define G1_LOAD_A(dst, s_)                                                       \
    do {                                                                         \
        _Pragma("unroll")                                                        \
        for (int sub = 0; sub < 2; sub++)                                        \
            _Pragma("unroll")                                                    \
            for (int p = 0; p < 2; p++)                                          \
                _Pragma("unroll")                                                \
                for (int q = 0; q < 2; q++) {                                    \
                    int kidx = (s_) * 32 + sub * 16 + tig * 2 + q * 8;           \
                    (dst)[sub][p][q] = rokg[p]                                   \
                        ? __ldg((const float2*)&X[(size_t)rowi[p] * NFEAT + kidx]) \
                        : make_float2(0.f, 0.f);                                 \
                }                                                                \
    } while (0)

    float2 srcA[2][2][2], srcB[2][2][2];
    G1_LOAD_A(srcA, 0);
    G1_PREFETCH(0, 0);

    for (int s = 0; s < 8; s++) {
        if (s + 1 < 8) {
            G1_PREFETCH((s + 1) & 1, s + 1);
            if (s & 1) G1_LOAD_A(srcA, s + 1); else G1_LOAD_A(srcB, s + 1);
            cpa_wait1();
        } else {
            cpa_wait0();
        }
        __syncthreads();

        float2 (*cur)[2][2] = (s & 1) ? srcB : srcA;
        const uint2* Bst = (const uint2*)&sB[s & 1][0];
#pragma unroll
        for (int sub = 0; sub < 2; sub++) {
            uint32_t ah[4];
            ah[0] = packf16(cur[sub][0][0]);
            ah[1] = packf16(cur[sub][1][0]);
            ah[2] = packf16(cur[sub][0][1]);
            ah[3] = packf16(cur[sub][1][1]);
#pragma unroll
            for (int c = 0; c < 8; c++) {
                int ctg = ctb + c;
                uint2 bv = Bst[sub * 512 + ctg * 32 + lane];
                MMA_F16(acc[c], ah[0], ah[1], ah[2], ah[3], bv.x, bv.y);
            }
        }
        __syncthreads();
    }

#pragma unroll
    for (int c = 0; c < 8; c++) {
        int col = wcol + c * 8 + tig * 2;
        if (rokg[0])
            *(uint32_t*)&g_s1h[(size_t)rowi[0] * NHID + col] =
                packf16(make_float2(acc[c][0], acc[c][1]));
        if (rokg[1])
            *(uint32_t*)&g_s1h[(size_t)rowi[1] * NHID + col] =
                packf16(make_float2(acc[c][2], acc[c][3]));
    }
#undef G1_PREFETCH
#undef G1_LOAD_A
}

// ---------------- SpMM1 + bias + ReLU (warp/row, fp16 gathers, 2-edge) ----------------
__global__ void spmm1_kernel(const int* __restrict__ acol, const float* __restrict__ aval,
                             const float* __restrict__ b1) {
    int warp = (blockIdx.x * blockDim.x + threadIdx.x) >> 5;
    int lane = threadIdx.x & 31;
    if (warp >= NN) return;

    int s = g_rowptr[warp];
    int e = g_rowptr[warp + 1];

    const char* S1b = (const char*)g_s1h + (size_t)lane * 8;   // row stride 256B
    unsigned long long a01 = 0ull, a23 = 0ull;

    int i = s;
    if ((i & 1) && i < e) {
        int   c = __ldcs(&acol[i]);
        float v = __ldcs(&aval[i]);
        unsigned long long w = ldg64cg(S1b + (size_t)c * 256);
        unsigned long long vv = dup2(v);
        a01 = ffma2(vv, packf2(unpackf16((uint32_t)w)), a01);
        a23 = ffma2(vv, packf2(unpackf16((uint32_t)(w >> 32))), a23);
        i++;
    }
    for (; i + 1 < e; i += 2) {
        int2   c2 = __ldcs((const int2*)&acol[i]);
        float2 v2 = __ldcs((const float2*)&aval[i]);
        unsigned long long w0 = ldg64cg(S1b + (size_t)c2.x * 256);
        unsigned long long w1 = ldg64cg(S1b + (size_t)c2.y * 256);
        unsigned long long vx = dup2(v2.x), vy = dup2(v2.y);
        a01 = ffma2(vx, packf2(unpackf16((uint32_t)w0)), a01);
        a23 = ffma2(vx, packf2(unpackf16((uint32_t)(w0 >> 32))), a23);
        a01 = ffma2(vy, packf2(unpackf16((uint32_t)w1)), a01);
        a23 = ffma2(vy, packf2(unpackf16((uint32_t)(w1 >> 32))), a23);
    }
    if (i < e) {
        int   c = __ldcs(&acol[i]);
        float v = __ldcs(&aval[i]);
        unsigned long long w = ldg64cg(S1b + (size_t)c * 256);
        unsigned long long vv = dup2(v);
        a01 = ffma2(vv, packf2(unpackf16((uint32_t)w)), a01);
        a23 = ffma2(vv, packf2(unpackf16((uint32_t)(w >> 32))), a23);
    }

    float2 p01 = unpack2(a01), p23 = unpack2(a23);
    float4 b = ((const float4*)b1)[lane];
    float4 r;
    r.x = fmaxf(p01.x + b.x, 0.f);
    r.y = fmaxf(p01.y + b.y, 0.f);
    r.z = fmaxf(p23.x + b.z, 0.f);
    r.w = fmaxf(p23.y + b.w, 0.f);
    uint2 pv;
    pv.x = packf16(make_float2(r.x, r.y));
    pv.y = packf16(make_float2(r.z, r.w));
    *(uint2*)((char*)g_hh + (size_t)warp * 256 + lane * 8) = pv;
}

// ---------------- GEMM2: s2h = fp16(h @ W2) (fp16 h stream, BM=256, BK=8, 2-stage) ----------------
#define G2_BM 256
#define G2_BK 8
#define G2_NT (NHID / G2_BK)     // 16
__global__ void __launch_bounds__(256) gemm2_kernel(const float* __restrict__ W2) {
    __shared__ uint32_t Hs[2][G2_BM * 4];     // 2 stages x 256 rows x 8 fp16 (4KB each)
    __shared__ float2   Wp[NHID * 20];        // 20 KB

    const int tid = threadIdx.x;
    const int pg  = tid & 3;
    const int rg  = tid >> 2;
    const int row0 = blockIdx.x * G2_BM;

    for (int j = tid; j < NHID * 20; j += 256) {
        int k = j / 20, p = j % 20;
        Wp[j] = *(const float2*)&W2[k * NCLASS + 2 * p];
    }

    unsigned hsb = (unsigned)__cvta_generic_to_shared(&Hs[0][0]);

#define G2_PREFETCH(stage, k0)                                                     \
    do {                                                                           \
        int grow = row0 + tid;                                                     \
        cpa16(hsb + (stage) * 4096 + tid * 16,                                     \
              (const char*)g_hh + (size_t)grow * 256 + (k0) * 2, grow < NN);       \
        cpa_commit();                                                              \
    } while (0)

    G2_PREFETCH(0, 0);

    unsigned long long acc[4][5];
#pragma unroll
    for (int i = 0; i < 4; i++)
#pragma unroll
        for (int j = 0; j < 5; j++) acc[i][j] = 0ull;

    for (int t = 0; t < G2_NT; t++) {
        if (t + 1 < G2_NT) {
            G2_PREFETCH((t + 1) & 1, (t + 1) * G2_BK);
            cpa_wait1();
        } else {
            cpa_wait0();
        }
        __syncthreads();

        const int st = t & 1;
        const int kbase = t * G2_BK;
#pragma unroll
        for (int kp = 0; kp < 4; kp++) {
            float2 hf[4];
#pragma unroll
            for (int i = 0; i < 4; i++)
                hf[i] = unpackf16(Hs[st][(rg + 64 * i) * 4 + kp]);
#pragma unroll
            for (int half = 0; half < 2; half++) {
                int kk = kbase + 2 * kp + half;
                unsigned long long wv[5];
#pragma unroll
                for (int j = 0; j < 5; j++)
                    wv[j] = *(const unsigned long long*)&Wp[kk * 20 + pg * 5 + j];
                unsigned long long hd[4];
#pragma unroll
                for (int i = 0; i < 4; i++)
                    hd[i] = dup2(half ? hf[i].y : hf[i].x);
#pragma unroll
                for (int i = 0; i < 4; i++)
#pragma unroll
                    for (int j = 0; j < 5; j++)
                        acc[i][j] = ffma2(hd[i], wv[j], acc[i][j]);
            }
        }
        __syncthreads();
    }

#pragma unroll
    for (int i = 0; i < 4; i++) {
        int grow = row0 + rg + 64 * i;
        if (grow < NN) {
#pragma unroll
            for (int j = 0; j < 5; j++) {
                float2 v = unpack2(acc[i][j]);
                *(uint32_t*)((char*)g_s2h + (size_t)grow * 80 + (pg * 5 + j) * 4) = packf16(v);
            }
        }
    }
#undef G2_PREFETCH
}

// ---------------- SpMM2 + bias + log_softmax (fp16 gathers, 3 slots x 2-deep) ----------------
__global__ void spmm2_lsm_kernel(const int* __restrict__ acol, const float* __restrict__ aval,
                                 const float* __restrict__ b2, float* __restrict__ out) {
    int warp = (blockIdx.x * blockDim.x + threadIdx.x) >> 5;
    int lane = threadIdx.x & 31;
    if (warp >= NN) return;

    int s = g_rowptr[warp];
    int e = g_rowptr[warp + 1];

    const int slot = lane / 10;          // 0,1,2 (lanes 30,31 inactive)
    const int seg  = lane - slot * 10;   // 0..9
    const bool lact = lane < 30;

    const char* S2b = (const char*)g_s2h + (size_t)seg * 8;   // row stride 80B
    unsigned long long acc0 = 0ull, acc1 = 0ull;

    int i = s;
    for (; i + 5 < e; i += 6) {
        int ei0 = i + slot, ei1 = i + 3 + slot;
        int c0 = 0, c1 = 0;
        float v0 = 0.f, v1 = 0.f;
        unsigned long long wa = 0ull, wb = 0ull;
        if (lact) {
            c0 = __ldcs(&acol[ei0]);
            c1 = __ldcs(&acol[ei1]);
            v0 = __ldcs(&aval[ei0]);
            v1 = __ldcs(&aval[ei1]);
            wa = ldg64cg(S2b + (size_t)c0 * 80);
            wb = ldg64cg(S2b + (size_t)c1 * 80);
        }
        unsigned long long vv0 = dup2(v0), vv1 = dup2(v1);
        acc0 = ffma2(vv0, packf2(unpackf16((uint32_t)wa)), acc0);
        acc1 = ffma2(vv0, packf2(unpackf16((uint32_t)(wa >> 32))), acc1);
        acc0 = ffma2(vv1, packf2(unpackf16((uint32_t)wb)), acc0);
        acc1 = ffma2(vv1, packf2(unpackf16((uint32_t)(wb >> 32))), acc1);
    }
    for (; i < e; i += 3) {
        int ei = i + slot;
        bool ok = lact && (ei < e);
        int   c = 0;
        float v = 0.f;
        unsigned long long w = 0ull;
        if (ok) {
            c = __ldcs(&acol[ei]);
            v = __ldcs(&aval[ei]);
            w = ldg64cg(S2b + (size_t)c * 80);
        }
        unsigned long long vv = dup2(v);
        acc0 = ffma2(vv, packf2(unpackf16((uint32_t)w)), acc0);
        acc1 = ffma2(vv, packf2(unpackf16((uint32_t)(w >> 32))), acc1);
    }

    float2 a0 = unpack2(acc0), a1 = unpack2(acc1);
    float vals[4] = {a0.x, a0.y, a1.x, a1.y};
#pragma unroll
    for (int j = 0; j < 4; j++) {
        float v10 = __shfl_down_sync(0xFFFFFFFFu, vals[j], 10);
        float v20 = __shfl_down_sync(0xFFFFFFFFu, vals[j], 20);
        vals[j] = vals[j] + v10 + v20;
    }

    bool outl = lane < 10;
    if (outl) {
        float4 bb = __ldg((const float4*)&b2[4 * seg]);
        vals[0] += bb.x; vals[1] += bb.y; vals[2] += bb.z; vals[3] += bb.w;
    }

    float m = outl ? fmaxf(fmaxf(vals[0], vals[1]), fmaxf(vals[2], vals[3])) : -INFINITY;
#pragma unroll
    for (int off = 16; off > 0; off >>= 1)
        m = fmaxf(m, __shfl_xor_sync(0xFFFFFFFFu, m, off));

    float se = outl ? (expf(vals[0] - m) + expf(vals[1] - m) +
                       expf(vals[2] - m) + expf(vals[3] - m)) : 0.f;
#pragma unroll
    for (int off = 16; off > 0; off >>= 1)
        se += __shfl_xor_sync(0xFFFFFFFFu, se, off);

    float lse = m + logf(se);
    if (outl) {
        float4 o;
        o.x = vals[0] - lse; o.y = vals[1] - lse;
        o.z = vals[2] - lse; o.w = vals[3] - lse;
        *(float4*)&out[(size_t)warp * NCLASS + 4 * seg] = o;
    }
}

// ---------------- launch ----------------
extern "C" void kernel_launch(void* const* d_in, const int* in_sizes, int n_in,
                              void* d_out, int out_size) {
    const float* x    = (const float*)d_in[0];
    const int*   arow = (const int*)  d_in[1];
    const int*   acol = (const int*)  d_in[2];
    const float* aval = (const float*)d_in[3];
    // d_in[4] = i (unused)
    const float* W1 = (const float*)d_in[5];
    const float* b1 = (const float*)d_in[6];
    const float* W2 = (const float*)d_in[7];
    const float* b2 = (const float*)d_in[8];
    float* out = (float*)d_out;

    build_rowptr_kernel<<<(NN + 1 + 255) / 256, 256>>>(arow);
    w1f16_kernel<<<(NFEAT * NHID + 255) / 256, 256>>>(W1);
    gemm1_f16_kernel<<<(NN + 127) / 128, 512>>>(x);
    spmm1_kernel<<<(NN * 32 + 255) / 256, 256>>>(acol, aval, b1);
    gemm2_kernel<<<(NN + G2_BM - 1) / G2_BM, 256>>>(W2);
    spmm2_lsm_kernel<<<(NN * 32 + 255) / 256, 256>>>(acol, aval, b2, out);
}